// round 17
// baseline (speedup 1.0000x reference)
#include <cuda_runtime.h>
#include <cuda_fp16.h>

// Problem constants
#define Bc   4
#define Vc   5
#define Jc   15
#define Hc   128
#define Wc   240
#define NPTS 128000      // 80*80*20
#define HW   (Hc * Wc)

// One pixel = 16 fp16 joints = 32 bytes, 32B-aligned for LDG.256
struct alignas(32) Pix { uint4 a, b; };

// Transposed fp16 heatmaps: (B*V, H, W) pixels of 16 halves = 19.66 MB
__device__ Pix g_hmT[(size_t)Bc * Vc * HW];

static __device__ __forceinline__ unsigned pack_h2(float lo, float hi) {
    __half2 h = __floats2half2_rn(lo, hi);
    return *reinterpret_cast<unsigned*>(&h);
}

// ---------------------------------------------------------------------------
// Kernel 1: transpose (B,V,J,H,W) f32 -> (B*V, H*W) pixels of 16 f16.
// One thread per pixel: 15 coalesced strided loads, register pack,
// 2 coalesced 128-bit stores. At its ~10us HBM floor.
// ---------------------------------------------------------------------------
__global__ void __launch_bounds__(256) transpose_kernel(const float* __restrict__ hm) {
    const int idx = blockIdx.x * blockDim.x + threadIdx.x;
    if (idx < Bc * Vc * HW) {
        const int bv  = idx / HW;
        const int pix = idx - bv * HW;

        const float* src = hm + (size_t)bv * Jc * HW + pix;
        float v[16];
#pragma unroll
        for (int j = 0; j < Jc; ++j)
            v[j] = __ldg(src + (size_t)j * HW);
        v[15] = 0.0f;

        Pix p;
        p.a.x = pack_h2(v[0],  v[1]);
        p.a.y = pack_h2(v[2],  v[3]);
        p.a.z = pack_h2(v[4],  v[5]);
        p.a.w = pack_h2(v[6],  v[7]);
        p.b.x = pack_h2(v[8],  v[9]);
        p.b.y = pack_h2(v[10], v[11]);
        p.b.z = pack_h2(v[12], v[13]);
        p.b.w = pack_h2(v[14], v[15]);
        g_hmT[idx] = p;
    }
    // PDL: signal the dependent sample_kernel once this CTA's stores are done.
    cudaTriggerProgrammaticLaunchCompletion();
}

// ---------------------------------------------------------------------------
// 256-bit read-only global load (Blackwell LDG.E.256): one full pixel.
// ---------------------------------------------------------------------------
static __device__ __forceinline__ void ldg256(const Pix* p, float (&f)[8]) {
    asm volatile(
        "ld.global.nc.v8.f32 {%0,%1,%2,%3,%4,%5,%6,%7}, [%8];"
        : "=f"(f[0]), "=f"(f[1]), "=f"(f[2]), "=f"(f[3]),
          "=f"(f[4]), "=f"(f[5]), "=f"(f[6]), "=f"(f[7])
        : "l"(p));
}

// Scalar unpack + FMA (proven fastest datapath).
static __device__ __forceinline__ void acc_corner(float (&acc)[16],
                                                  const float (&f)[8], float w) {
#pragma unroll
    for (int i = 0; i < 8; ++i) {
        __half2 h = *reinterpret_cast<const __half2*>(&f[i]);
        float2 u = __half22float2(h);
        acc[2 * i + 0] = fmaf(w, u.x, acc[2 * i + 0]);
        acc[2 * i + 1] = fmaf(w, u.y, acc[2 * i + 1]);
    }
}

// ---------------------------------------------------------------------------
// Kernel 2: gather, lane-paired + 3-view software pipeline.
// TWO threads per (b, n): lane parity jl handles column x0+jl (contiguous
// 64B pair shares L1 wavefronts within one LDG.256). The view loop is
// triple-buffered: the prologue issues loads for views 0-2; iteration v
// consumes view v then issues view v+3 into the freed slot, keeping ~5
// loads in flight per thread. Reduction: keep-half butterfly (8 shfl);
// lane0 owns joints 0-7, lane1 owns joints 8-14.
// ---------------------------------------------------------------------------
__global__ void __launch_bounds__(256, 3) sample_kernel(const float* __restrict__ grid,
                                                        float* __restrict__ out) {
    const int tid = blockIdx.x * blockDim.x + threadIdx.x;  // 0 .. 2*B*NPTS-1
    const int pid = tid >> 1;        // point id
    const int jl  = tid & 1;         // lane role: 0 -> x0 column, 1 -> x1 column
    const int b   = pid / NPTS;
    const int n   = pid - b * NPTS;

    // PDL prologue: grid coords do NOT depend on the transpose — load them
    // before the dependency sync so these LDGs overlap the transpose kernel.
    const float2* g2 = reinterpret_cast<const float2*>(grid);
    float2 g[Vc];
#pragma unroll
    for (int v = 0; v < Vc; ++v)
        g[v] = g2[(size_t)(b * Vc + v) * NPTS + n];

    float acc[16];
#pragma unroll
    for (int i = 0; i < 16; ++i) acc[i] = 0.0f;

    cudaGridDependencySynchronize();

    const Pix* hbase = g_hmT + (size_t)b * Vc * HW;

    // Compute this lane's two corner addresses + weights for view v.
    auto prep = [&](int v, const Pix*& q0, const Pix*& q1,
                    float& w0, float& w1) {
        const float ix = (g[v].x + 1.0f) * 0.5f * (float)(Wc - 1);
        const float iy = (g[v].y + 1.0f) * 0.5f * (float)(Hc - 1);
        const float x0f = floorf(ix);
        const float y0f = floorf(iy);
        const float wx1 = ix - x0f;
        const float wy1 = iy - y0f;

        int x0 = (int)x0f;
        int y0 = (int)y0f;
        x0 = max(0, min(x0, Wc - 1));
        y0 = max(0, min(y0, Hc - 1));
        const int xc = min(x0 + jl, Wc - 1);   // this lane's column
        const int y1 = min(y0 + 1, Hc - 1);

        const float wx = jl ? wx1 : (1.0f - wx1);
        w0 = wx * (1.0f - wy1);
        w1 = wx * wy1;

        const Pix* base = hbase + (size_t)v * HW;
        q0 = base + (unsigned)(y0 * Wc + xc);
        q1 = base + (unsigned)(y1 * Wc + xc);
    };

    // Triple-buffered pipeline over views.
    float f0[3][8], f1[3][8];
    float w0v[3], w1v[3];
#pragma unroll
    for (int v = 0; v < 3; ++v) {
        const Pix *q0, *q1;
        prep(v, q0, q1, w0v[v], w1v[v]);
        ldg256(q0, f0[v]);
        ldg256(q1, f1[v]);
    }
#pragma unroll
    for (int v = 0; v < Vc; ++v) {
        const int slot = v % 3;
        acc_corner(acc, f0[slot], w0v[slot]);   // consume view v ...
        acc_corner(acc, f1[slot], w1v[slot]);
        if (v + 3 < Vc) {                       // ... then refill the slot
            const Pix *q0, *q1;
            prep(v + 3, q0, q1, w0v[slot], w1v[slot]);
            ldg256(q0, f0[slot]);
            ldg256(q1, f1[slot]);
        }
    }

    // Keep-half butterfly: lane jl keeps joints [jl*8, jl*8+8).
    float r[8];
#pragma unroll
    for (int i = 0; i < 8; ++i) {
        const float send = jl ? acc[i] : acc[i + 8];
        const float keep = jl ? acc[i + 8] : acc[i];
        r[i] = keep + __shfl_xor_sync(0xffffffffu, send, 1);
    }

    const int jbase = jl * 8;
    const float s = 1.0f / (float)Vc;
    float* op = out + (size_t)b * Jc * NPTS + n;
#pragma unroll
    for (int k = 0; k < 8; ++k) {
        if (jbase + k < Jc) {
            float val = r[k] * s;
            val = fminf(fmaxf(val, 0.0f), 1.0f);
            op[(size_t)(jbase + k) * NPTS] = val;
        }
    }
}

// ---------------------------------------------------------------------------
extern "C" void kernel_launch(void* const* d_in, const int* in_sizes, int n_in,
                              void* d_out, int out_size) {
    const float* heatmaps = (const float*)d_in[0];  // (4,5,15,128,240) f32
    const float* grid     = (const float*)d_in[1];  // (4,5,1,128000,2) f32
    float* out            = (float*)d_out;          // (4,15,80,80,20) f32

    (void)in_sizes; (void)n_in; (void)out_size;

    const int tp_total = Bc * Vc * HW;              // 614400
    transpose_kernel<<<(tp_total + 255) / 256, 256>>>(heatmaps);

    // Sample kernel as a programmatic dependent launch: its grid-load
    // prologue overlaps the transpose; cudaGridDependencySynchronize()
    // inside the kernel enforces ordering before g_hmT is read.
    const int total = Bc * NPTS * 2;                // 1,024,000
    cudaLaunchConfig_t cfg = {};
    cfg.gridDim  = dim3((total + 255) / 256);
    cfg.blockDim = dim3(256);
    cfg.dynamicSmemBytes = 0;
    cudaLaunchAttribute attr[1];
    attr[0].id = cudaLaunchAttributeProgrammaticStreamSerialization;
    attr[0].val.programmaticStreamSerializationAllowed = 1;
    cfg.attrs = attr;
    cfg.numAttrs = 1;
    cudaLaunchKernelEx(&cfg, sample_kernel, grid, out);
}